// round 1
// baseline (speedup 1.0000x reference)
#include <cuda_runtime.h>
#include <math.h>

// ---------------- problem constants ----------------
#define cN 10000     // nodes
#define cE 40000     // edges
#define cD 64        // feature dim
#define cB 512       // batch (graphs)
#define cFIN 11
#define cEF 5
#define cH 128       // edge-net hidden
#define cDSQ 4096    // D*D

// ---------------- device scratch (no allocs allowed) ----------------
__device__ float g_h0[cN * cD];
__device__ float g_h1[cN * cD];
__device__ float g_hrelu[cE * cH];          // 20 MB
__device__ float g_ew[cE * cDSQ];           // 655 MB edge weights [E,64,64]
__device__ float g_agg[cN * cD];
__device__ float g_m[cN * cD];
__device__ float g_croot[cN * cD];
__device__ float g_G1[cN * 3 * cD];
__device__ float g_G2[cN * 3 * cD];
__device__ float g_deg[cN];
__device__ float g_esc[cN];
__device__ unsigned g_emaxu[cB];
__device__ float g_esum[cB];
__device__ float g_rvec[cB * cD];
__device__ float g_qsA[cB * 2 * cD];
__device__ float g_qsB[cB * 2 * cD];
__device__ float g_hlA[cB * cD];
__device__ float g_hlB[cB * cD];
__device__ float g_clA[cB * cD];
__device__ float g_clB[cB * cD];

// ---------------- helpers ----------------
__device__ __forceinline__ float sigm(float x) { return 1.0f / (1.0f + expf(-x)); }

// monotone float<->uint encoding for atomicMax on floats
__device__ __forceinline__ unsigned f2u(float f) {
    unsigned u = __float_as_uint(f);
    return (u & 0x80000000u) ? ~u : (u | 0x80000000u);
}
__device__ __forceinline__ float u2f(unsigned u) {
    return __uint_as_float((u & 0x80000000u) ? (u ^ 0x80000000u) : ~u);
}

// ---------------- generic kernels ----------------
__global__ void k_zero(float* p, int n) {
    int i = blockIdx.x * blockDim.x + threadIdx.x;
    if (i < n) p[i] = 0.0f;
}

__global__ void k_deg_zero(float* deg) {
    int i = blockIdx.x * blockDim.x + threadIdx.x;
    if (i < cN) deg[i] = 0.0f;
}

__global__ void k_deg(const int* __restrict__ dst, float* deg) {
    int e = blockIdx.x * blockDim.x + threadIdx.x;
    if (e < cE) atomicAdd(&deg[dst[e]], 1.0f);
}

// out = relu(x @ lin0_w + lin0_b)  -> writes h0
__global__ void k_lin0(const float* __restrict__ x, const float* __restrict__ w,
                       const float* __restrict__ b, float* __restrict__ h0) {
    int idx = blockIdx.x * blockDim.x + threadIdx.x;
    if (idx >= cN * cD) return;
    int n = idx >> 6, d = idx & 63;
    float acc = b[d];
    const float* xr = x + n * cFIN;
#pragma unroll
    for (int i = 0; i < cFIN; i++) acc += xr[i] * w[i * cD + d];
    h0[idx] = fmaxf(acc, 0.0f);
}

// hrelu = relu(edge_attr @ net_w1 + net_b1)
__global__ void k_edge1(const float* __restrict__ ea, const float* __restrict__ w1,
                        const float* __restrict__ b1, float* __restrict__ hrelu) {
    int idx = blockIdx.x * blockDim.x + threadIdx.x;
    if (idx >= cE * cH) return;
    int e = idx >> 7, j = idx & 127;
    float acc = b1[j];
    const float* er = ea + e * cEF;
#pragma unroll
    for (int i = 0; i < cEF; i++) acc += er[i] * w1[i * cH + j];
    hrelu[idx] = fmaxf(acc, 0.0f);
}

// -------- generic tiled SGEMM: C[M,Nc] = A[M,K] @ B[K,Nc] (+bias) --------
template <int BM, int BN, int BK, int TM, int TN>
__global__ void sgemm(int M, int Nc, int K,
                      const float* __restrict__ A, const float* __restrict__ Bw,
                      const float* __restrict__ bias, float* __restrict__ C) {
    constexpr int NT = (BM / TM) * (BN / TN);
    __shared__ float As[BK][BM];
    __shared__ float Bs[BK][BN];
    const int tid = threadIdx.x;
    const int tcn = BN / TN;
    const int tr = tid / tcn, tc = tid % tcn;
    const int rowBase = blockIdx.y * BM, colBase = blockIdx.x * BN;

    float acc[TM][TN];
#pragma unroll
    for (int i = 0; i < TM; i++)
#pragma unroll
        for (int j = 0; j < TN; j++) acc[i][j] = 0.0f;

    for (int k0 = 0; k0 < K; k0 += BK) {
#pragma unroll
        for (int i = tid; i < BM * BK; i += NT) {
            int r = i / BK, kk = i % BK;
            int gr = rowBase + r;
            As[kk][r] = (gr < M) ? A[(size_t)gr * K + k0 + kk] : 0.0f;
        }
#pragma unroll
        for (int i = tid; i < BK * BN; i += NT) {
            int kk = i / BN, c = i % BN;
            int gc = colBase + c;
            Bs[kk][c] = (gc < Nc) ? Bw[(size_t)(k0 + kk) * Nc + gc] : 0.0f;
        }
        __syncthreads();
#pragma unroll
        for (int kk = 0; kk < BK; kk++) {
            float ra[TM], rb[TN];
#pragma unroll
            for (int i = 0; i < TM; i++) ra[i] = As[kk][tr * TM + i];
#pragma unroll
            for (int j = 0; j < TN; j++) rb[j] = Bs[kk][tc * TN + j];
#pragma unroll
            for (int i = 0; i < TM; i++)
#pragma unroll
                for (int j = 0; j < TN; j++) acc[i][j] += ra[i] * rb[j];
        }
        __syncthreads();
    }
#pragma unroll
    for (int i = 0; i < TM; i++) {
        int r = rowBase + tr * TM + i;
        if (r >= M) continue;
#pragma unroll
        for (int j = 0; j < TN; j++) {
            int c = colBase + tc * TN + j;
            if (c >= Nc) continue;
            float v = acc[i][j] + (bias ? bias[c] : 0.0f);
            C[(size_t)r * Nc + c] = v;
        }
    }
}

// -------- per-edge matvec + scatter: agg[dst] += out[src] @ ew[e] --------
// one warp per edge; lane covers output cols lane and lane+32
__global__ void k_msg(const float* __restrict__ out, const float* __restrict__ ew,
                      const int* __restrict__ src, const int* __restrict__ dst,
                      float* __restrict__ agg) {
    int e = blockIdx.x * blockDim.y + threadIdx.y;
    if (e >= cE) return;
    int lane = threadIdx.x;
    int s = src[e];
    const float* vo = out + s * cD;
    const float* w = ew + (size_t)e * cDSQ;
    float a0 = 0.0f, a1 = 0.0f;
#pragma unroll 8
    for (int i = 0; i < cD; i++) {
        float v = __ldg(vo + i);
        a0 += v * w[i * cD + lane];
        a1 += v * w[i * cD + 32 + lane];
    }
    int dn = dst[e];
    atomicAdd(&agg[dn * cD + lane], a0);
    atomicAdd(&agg[dn * cD + 32 + lane], a1);
}

// m = relu(agg/deg + croot + conv_bias)
__global__ void k_m(const float* __restrict__ agg, const float* __restrict__ croot,
                    const float* __restrict__ deg, const float* __restrict__ cbias,
                    float* __restrict__ m) {
    int idx = blockIdx.x * blockDim.x + threadIdx.x;
    if (idx >= cN * cD) return;
    int n = idx >> 6, d = idx & 63;
    float dg = fmaxf(deg[n], 1.0f);
    float v = agg[idx] / dg + croot[idx] + cbias[d];
    m[idx] = fmaxf(v, 0.0f);
}

// GRU gate math: G1 = m@W_ih + b_ih [N,192], G2 = h@W_hh + b_hh [N,192]
__global__ void k_gate(const float* __restrict__ G1, const float* __restrict__ G2,
                       const float* __restrict__ h, float* __restrict__ hn) {
    int idx = blockIdx.x * blockDim.x + threadIdx.x;
    if (idx >= cN * cD) return;
    int n = idx >> 6, d = idx & 63;
    const float* g1 = G1 + n * 3 * cD;
    const float* g2 = G2 + n * 3 * cD;
    float r = sigm(g1[d] + g2[d]);
    float z = sigm(g1[cD + d] + g2[cD + d]);
    float nn = tanhf(g1[2 * cD + d] + r * g2[2 * cD + d]);
    hn[idx] = (1.0f - z) * nn + z * h[idx];
}

// ---------------- Set2Set ----------------
__global__ void k_s2s_init(float* qsA, float* hlA, float* clA) {
    int i = blockIdx.x * blockDim.x + threadIdx.x;
    if (i < cB * 2 * cD) qsA[i] = 0.0f;
    if (i < cB * cD) { hlA[i] = 0.0f; clA[i] = 0.0f; }
}

__global__ void k_lstm(const float* __restrict__ qs, const float* __restrict__ hl,
                       const float* __restrict__ cl,
                       const float* __restrict__ w_ih, const float* __restrict__ w_hh,
                       const float* __restrict__ b_ih, const float* __restrict__ b_hh,
                       float* __restrict__ hl_n, float* __restrict__ cl_n) {
    int idx = blockIdx.x * blockDim.x + threadIdx.x;
    if (idx >= cB * cD) return;
    int b = idx >> 6, d = idx & 63;
    float acc0 = b_ih[d] + b_hh[d];
    float acc1 = b_ih[cD + d] + b_hh[cD + d];
    float acc2 = b_ih[2 * cD + d] + b_hh[2 * cD + d];
    float acc3 = b_ih[3 * cD + d] + b_hh[3 * cD + d];
    const float* q = qs + b * 2 * cD;
#pragma unroll 4
    for (int k = 0; k < 2 * cD; k++) {
        float qv = q[k];
        const float* wr = w_ih + k * 4 * cD;
        acc0 += qv * wr[d];
        acc1 += qv * wr[cD + d];
        acc2 += qv * wr[2 * cD + d];
        acc3 += qv * wr[3 * cD + d];
    }
    const float* hr = hl + b * cD;
#pragma unroll 4
    for (int k = 0; k < cD; k++) {
        float hv = hr[k];
        const float* wr = w_hh + k * 4 * cD;
        acc0 += hv * wr[d];
        acc1 += hv * wr[cD + d];
        acc2 += hv * wr[2 * cD + d];
        acc3 += hv * wr[3 * cD + d];
    }
    float ig = sigm(acc0), fg = sigm(acc1), gg = tanhf(acc2), og = sigm(acc3);
    float c = fg * cl[idx] + ig * gg;
    cl_n[idx] = c;
    hl_n[idx] = og * tanhf(c);
}

__global__ void k_zero_bat(unsigned* emaxu, float* esum, float* rvec) {
    int i = blockIdx.x * blockDim.x + threadIdx.x;
    if (i < cB) { emaxu[i] = 0u; esum[i] = 0.0f; }
    if (i < cB * cD) rvec[i] = 0.0f;
}

__global__ void k_attn1(const float* __restrict__ out, const int* __restrict__ batch,
                        const float* __restrict__ hl, float* __restrict__ esc,
                        unsigned* __restrict__ emaxu) {
    int n = blockIdx.x * blockDim.x + threadIdx.x;
    if (n >= cN) return;
    int b = batch[n];
    const float* o = out + n * cD;
    const float* q = hl + b * cD;
    float acc = 0.0f;
#pragma unroll 8
    for (int d = 0; d < cD; d++) acc += o[d] * q[d];
    esc[n] = acc;
    atomicMax(&emaxu[b], f2u(acc));
}

__global__ void k_attn2(const int* __restrict__ batch, float* __restrict__ esc,
                        const unsigned* __restrict__ emaxu, float* __restrict__ esum) {
    int n = blockIdx.x * blockDim.x + threadIdx.x;
    if (n >= cN) return;
    int b = batch[n];
    float ee = expf(esc[n] - u2f(emaxu[b]));
    esc[n] = ee;
    atomicAdd(&esum[b], ee);
}

__global__ void k_attn3(const float* __restrict__ out, const int* __restrict__ batch,
                        const float* __restrict__ esc, const float* __restrict__ esum,
                        float* __restrict__ rvec) {
    int idx = blockIdx.x * blockDim.x + threadIdx.x;
    if (idx >= cN * cD) return;
    int n = idx >> 6, d = idx & 63;
    int b = batch[n];
    float a = esc[n] / esum[b];
    atomicAdd(&rvec[b * cD + d], a * out[idx]);
}

__global__ void k_qstar(const float* __restrict__ hl, const float* __restrict__ rvec,
                        float* __restrict__ qs_n) {
    int idx = blockIdx.x * blockDim.x + threadIdx.x;
    if (idx >= cB * 2 * cD) return;
    int b = idx >> 7, c = idx & 127;
    qs_n[idx] = (c < cD) ? hl[b * cD + c] : rvec[b * cD + (c - cD)];
}

__global__ void k_lin1(const float* __restrict__ qs, const float* __restrict__ w,
                       const float* __restrict__ b, float* __restrict__ out) {
    int idx = blockIdx.x * blockDim.x + threadIdx.x;
    if (idx >= cB * cD) return;
    int bb = idx >> 6, d = idx & 63;
    float acc = b[d];
    const float* q = qs + bb * 2 * cD;
#pragma unroll 8
    for (int k = 0; k < 2 * cD; k++) acc += q[k] * w[k * cD + d];
    out[idx] = fmaxf(acc, 0.0f);
}

// ---------------- launch ----------------
extern "C" void kernel_launch(void* const* d_in, const int* in_sizes, int n_in,
                              void* d_out, int out_size) {
    const float* x        = (const float*)d_in[0];
    const float* ea       = (const float*)d_in[1];
    const int*   ei       = (const int*)d_in[2];
    const int*   batch    = (const int*)d_in[3];
    const float* lin0_w   = (const float*)d_in[4];
    const float* lin0_b   = (const float*)d_in[5];
    const float* net_w1   = (const float*)d_in[6];
    const float* net_b1   = (const float*)d_in[7];
    const float* net_w2   = (const float*)d_in[8];
    const float* net_b2   = (const float*)d_in[9];
    const float* conv_root= (const float*)d_in[10];
    const float* conv_bias= (const float*)d_in[11];
    const float* gru_w_ih = (const float*)d_in[12];
    const float* gru_w_hh = (const float*)d_in[13];
    const float* gru_b_ih = (const float*)d_in[14];
    const float* gru_b_hh = (const float*)d_in[15];
    const float* lstm_w_ih= (const float*)d_in[16];
    const float* lstm_w_hh= (const float*)d_in[17];
    const float* lstm_b_ih= (const float*)d_in[18];
    const float* lstm_b_hh= (const float*)d_in[19];
    const float* lin1_w   = (const float*)d_in[20];
    const float* lin1_b   = (const float*)d_in[21];
    float* out = (float*)d_out;

    const int* src = ei;
    const int* dst = ei + cE;

    // fetch scratch addresses
    void* p;
    cudaGetSymbolAddress(&p, g_h0);    float* p_h0 = (float*)p;
    cudaGetSymbolAddress(&p, g_h1);    float* p_h1 = (float*)p;
    cudaGetSymbolAddress(&p, g_hrelu); float* p_hr = (float*)p;
    cudaGetSymbolAddress(&p, g_ew);    float* p_ew = (float*)p;
    cudaGetSymbolAddress(&p, g_agg);   float* p_agg = (float*)p;
    cudaGetSymbolAddress(&p, g_m);     float* p_m = (float*)p;
    cudaGetSymbolAddress(&p, g_croot); float* p_cr = (float*)p;
    cudaGetSymbolAddress(&p, g_G1);    float* p_G1 = (float*)p;
    cudaGetSymbolAddress(&p, g_G2);    float* p_G2 = (float*)p;
    cudaGetSymbolAddress(&p, g_deg);   float* p_deg = (float*)p;
    cudaGetSymbolAddress(&p, g_esc);   float* p_esc = (float*)p;
    cudaGetSymbolAddress(&p, g_emaxu); unsigned* p_emax = (unsigned*)p;
    cudaGetSymbolAddress(&p, g_esum);  float* p_esum = (float*)p;
    cudaGetSymbolAddress(&p, g_rvec);  float* p_rvec = (float*)p;
    cudaGetSymbolAddress(&p, g_qsA);   float* p_qsA = (float*)p;
    cudaGetSymbolAddress(&p, g_qsB);   float* p_qsB = (float*)p;
    cudaGetSymbolAddress(&p, g_hlA);   float* p_hlA = (float*)p;
    cudaGetSymbolAddress(&p, g_hlB);   float* p_hlB = (float*)p;
    cudaGetSymbolAddress(&p, g_clA);   float* p_clA = (float*)p;
    cudaGetSymbolAddress(&p, g_clB);   float* p_clB = (float*)p;

    const int T = 256;

    // degree
    k_deg_zero<<<(cN + T - 1) / T, T>>>(p_deg);
    k_deg<<<(cE + T - 1) / T, T>>>(dst, p_deg);

    // lin0 -> h0 (out == h)
    k_lin0<<<(cN * cD + T - 1) / T, T>>>(x, lin0_w, lin0_b, p_h0);

    // edge network
    k_edge1<<<(cE * cH + T - 1) / T, T>>>(ea, net_w1, net_b1, p_hr);
    {
        dim3 grid(cDSQ / 128, (cE + 127) / 128);
        sgemm<128, 128, 8, 8, 8><<<grid, 256>>>(cE, cDSQ, cH, p_hr, net_w2, net_b2, p_ew);
    }

    // 3 message-passing steps, ping-pong h between h0/h1
    for (int s = 0; s < 3; s++) {
        float* cur = (s & 1) ? p_h1 : p_h0;
        float* nxt = (s & 1) ? p_h0 : p_h1;
        k_zero<<<(cN * cD + T - 1) / T, T>>>(p_agg, cN * cD);
        {
            dim3 blk(32, 8);
            k_msg<<<(cE + 7) / 8, blk>>>(cur, p_ew, src, dst, p_agg);
        }
        {
            dim3 grid((cD + 63) / 64, (cN + 63) / 64);
            sgemm<64, 64, 8, 4, 4><<<grid, 256>>>(cN, cD, cD, cur, conv_root, (const float*)0, p_cr);
        }
        k_m<<<(cN * cD + T - 1) / T, T>>>(p_agg, p_cr, p_deg, conv_bias, p_m);
        {
            dim3 grid((3 * cD + 63) / 64, (cN + 63) / 64);
            sgemm<64, 64, 8, 4, 4><<<grid, 256>>>(cN, 3 * cD, cD, p_m, gru_w_ih, gru_b_ih, p_G1);
            sgemm<64, 64, 8, 4, 4><<<grid, 256>>>(cN, 3 * cD, cD, cur, gru_w_hh, gru_b_hh, p_G2);
        }
        k_gate<<<(cN * cD + T - 1) / T, T>>>(p_G1, p_G2, cur, nxt);
    }
    float* p_hfin = p_h1;  // after steps 0(h0->h1),1(h1->h0),2(h0->h1)

    // Set2Set: 3 iterations, ping-pong A/B
    k_s2s_init<<<(cB * 2 * cD + T - 1) / T, T>>>(p_qsA, p_hlA, p_clA);
    for (int t = 0; t < 3; t++) {
        float* qs_c = (t & 1) ? p_qsB : p_qsA;
        float* qs_n = (t & 1) ? p_qsA : p_qsB;
        float* hl_c = (t & 1) ? p_hlB : p_hlA;
        float* hl_n = (t & 1) ? p_hlA : p_hlB;
        float* cl_c = (t & 1) ? p_clB : p_clA;
        float* cl_n = (t & 1) ? p_clA : p_clB;

        k_lstm<<<(cB * cD + T - 1) / T, T>>>(qs_c, hl_c, cl_c, lstm_w_ih, lstm_w_hh,
                                             lstm_b_ih, lstm_b_hh, hl_n, cl_n);
        k_zero_bat<<<(cB * cD + T - 1) / T, T>>>(p_emax, p_esum, p_rvec);
        k_attn1<<<(cN + T - 1) / T, T>>>(p_hfin, batch, hl_n, p_esc, p_emax);
        k_attn2<<<(cN + T - 1) / T, T>>>(batch, p_esc, p_emax, p_esum);
        k_attn3<<<(cN * cD + T - 1) / T, T>>>(p_hfin, batch, p_esc, p_esum, p_rvec);
        k_qstar<<<(cB * 2 * cD + T - 1) / T, T>>>(hl_n, p_rvec, qs_n);
    }

    // final linear (q_star ends in qsB after t=2)
    k_lin1<<<(cB * cD + T - 1) / T, T>>>(p_qsB, lin1_w, lin1_b, out);
}

// round 2
// speedup vs baseline: 2.1798x; 2.1798x over previous
#include <cuda_runtime.h>
#include <math.h>
#include <stdint.h>

// ---------------- problem constants ----------------
#define cN 10000     // nodes
#define cE 40000     // edges
#define cD 64        // feature dim
#define cB 512       // batch (graphs)
#define cFIN 11
#define cEF 5
#define cH 128       // edge-net hidden
#define cDSQ 4096    // D*D

// ---------------- device scratch (no allocs allowed) ----------------
__device__ float g_h0[cN * cD];
__device__ float g_h1[cN * cD];
__device__ float g_hrelu[cE * cH];          // 20 MB
__device__ float g_ew[cE * cDSQ];           // 655 MB edge weights [E,64,64]
__device__ float g_agg[cN * cD];
__device__ float g_m[cN * cD];
__device__ float g_croot[cN * cD];
__device__ float g_G1[cN * 3 * cD];
__device__ float g_G2[cN * 3 * cD];
__device__ float g_deg[cN];
__device__ float g_esc[cN];
__device__ unsigned g_emaxu[cB];
__device__ float g_esum[cB];
__device__ float g_rvec[cB * cD];
__device__ float g_qsA[cB * 2 * cD];
__device__ float g_qsB[cB * 2 * cD];
__device__ float g_hlA[cB * cD];
__device__ float g_hlB[cB * cD];
__device__ float g_clA[cB * cD];
__device__ float g_clB[cB * cD];

// ---------------- helpers ----------------
__device__ __forceinline__ float sigm(float x) { return 1.0f / (1.0f + expf(-x)); }

__device__ __forceinline__ unsigned f2u(float f) {
    unsigned u = __float_as_uint(f);
    return (u & 0x80000000u) ? ~u : (u | 0x80000000u);
}
__device__ __forceinline__ float u2f(unsigned u) {
    return __uint_as_float((u & 0x80000000u) ? (u ^ 0x80000000u) : ~u);
}

__device__ __forceinline__ uint32_t f2tf32(float f) {
    uint32_t u;
    asm("cvt.rna.tf32.f32 %0, %1;" : "=r"(u) : "f"(f));
    return u;
}

__device__ __forceinline__ void mma_tf32(float* d, const uint32_t* a, const uint32_t* b) {
    asm volatile(
        "mma.sync.aligned.m16n8k8.row.col.f32.tf32.tf32.f32 "
        "{%0,%1,%2,%3}, {%4,%5,%6,%7}, {%8,%9}, {%0,%1,%2,%3};"
        : "+f"(d[0]), "+f"(d[1]), "+f"(d[2]), "+f"(d[3])
        : "r"(a[0]), "r"(a[1]), "r"(a[2]), "r"(a[3]), "r"(b[0]), "r"(b[1]));
}

// ---------------- generic kernels ----------------
__global__ void k_zero(float* p, int n) {
    int i = blockIdx.x * blockDim.x + threadIdx.x;
    if (i < n) p[i] = 0.0f;
}

__global__ void k_deg_zero(float* deg) {
    int i = blockIdx.x * blockDim.x + threadIdx.x;
    if (i < cN) deg[i] = 0.0f;
}

__global__ void k_deg(const int* __restrict__ dst, float* deg) {
    int e = blockIdx.x * blockDim.x + threadIdx.x;
    if (e < cE) atomicAdd(&deg[dst[e]], 1.0f);
}

__global__ void k_lin0(const float* __restrict__ x, const float* __restrict__ w,
                       const float* __restrict__ b, float* __restrict__ h0) {
    int idx = blockIdx.x * blockDim.x + threadIdx.x;
    if (idx >= cN * cD) return;
    int n = idx >> 6, d = idx & 63;
    float acc = b[d];
    const float* xr = x + n * cFIN;
#pragma unroll
    for (int i = 0; i < cFIN; i++) acc += xr[i] * w[i * cD + d];
    h0[idx] = fmaxf(acc, 0.0f);
}

__global__ void k_edge1(const float* __restrict__ ea, const float* __restrict__ w1,
                        const float* __restrict__ b1, float* __restrict__ hrelu) {
    int idx = blockIdx.x * blockDim.x + threadIdx.x;
    if (idx >= cE * cH) return;
    int e = idx >> 7, j = idx & 127;
    float acc = b1[j];
    const float* er = ea + e * cEF;
#pragma unroll
    for (int i = 0; i < cEF; i++) acc += er[i] * w1[i * cH + j];
    hrelu[idx] = fmaxf(acc, 0.0f);
}

// -------- TF32 tensor-core GEMM for ew: C[E,4096] = A[E,128] @ B[128,4096] + bias --------
// CTA tile 128x128, 8 warps in 2x4 (warp tile 64x32), mma m16n8k8.
__global__ void __launch_bounds__(256) k_ewgemm(const float* __restrict__ A,
                                                const float* __restrict__ Bw,
                                                const float* __restrict__ bias,
                                                float* __restrict__ C) {
    __shared__ uint32_t As[32][132];   // [k][m], pad 132
    __shared__ uint32_t Bs[32][132];   // [k][n], pad 132

    const int tid = threadIdx.x;
    const int warp = tid >> 5, lane = tid & 31;
    const int wm = warp >> 2, wn = warp & 3;     // 2 x 4 warp grid
    const int g = lane >> 2, c = lane & 3;       // groupID, threadInGroup
    const int rowBase = blockIdx.y * 128;
    const int colBase = blockIdx.x * 128;

    float acc[4][4][4];
#pragma unroll
    for (int mt = 0; mt < 4; mt++)
#pragma unroll
        for (int nt = 0; nt < 4; nt++)
#pragma unroll
            for (int j = 0; j < 4; j++) acc[mt][nt][j] = 0.0f;

#pragma unroll
    for (int ck = 0; ck < 4; ck++) {
        const int k0 = ck * 32;
        // load A chunk [128 rows x 32 k] -> As[k][m] (tf32)
#pragma unroll
        for (int it = 0; it < 4; it++) {
            int idx = tid + it * 256;            // 0..1023
            int row = idx >> 3, kq = idx & 7;    // 8 float4 per row
            int grow = rowBase + row;
            float4 v = make_float4(0.f, 0.f, 0.f, 0.f);
            if (grow < cE) v = *(const float4*)(A + (size_t)grow * cH + k0 + kq * 4);
            As[kq * 4 + 0][row] = f2tf32(v.x);
            As[kq * 4 + 1][row] = f2tf32(v.y);
            As[kq * 4 + 2][row] = f2tf32(v.z);
            As[kq * 4 + 3][row] = f2tf32(v.w);
        }
        // load B chunk [32 k x 128 n] -> Bs[k][n] (tf32)
#pragma unroll
        for (int it = 0; it < 4; it++) {
            int idx = tid + it * 256;
            int kr = idx >> 5, nq = idx & 31;    // 32 float4 per k-row
            float4 v = *(const float4*)(Bw + (size_t)(k0 + kr) * cDSQ + colBase + nq * 4);
            uint4 u;
            u.x = f2tf32(v.x); u.y = f2tf32(v.y); u.z = f2tf32(v.z); u.w = f2tf32(v.w);
            *(uint4*)&Bs[kr][nq * 4] = u;
        }
        __syncthreads();

#pragma unroll
        for (int kk = 0; kk < 32; kk += 8) {
            uint32_t af[4][4];
#pragma unroll
            for (int mt = 0; mt < 4; mt++) {
                int r = wm * 64 + mt * 16 + g;
                af[mt][0] = As[kk + c][r];         // a0: (row g,   col c)
                af[mt][1] = As[kk + c][r + 8];     // a1: (row g+8, col c)
                af[mt][2] = As[kk + c + 4][r];     // a2: (row g,   col c+4)
                af[mt][3] = As[kk + c + 4][r + 8]; // a3: (row g+8, col c+4)
            }
            uint32_t bf[4][2];
#pragma unroll
            for (int nt = 0; nt < 4; nt++) {
                int n = wn * 32 + nt * 8 + g;
                bf[nt][0] = Bs[kk + c][n];         // b0: (k c,   n g)
                bf[nt][1] = Bs[kk + c + 4][n];     // b1: (k c+4, n g)
            }
#pragma unroll
            for (int mt = 0; mt < 4; mt++)
#pragma unroll
                for (int nt = 0; nt < 4; nt++)
                    mma_tf32(acc[mt][nt], af[mt], bf[nt]);
        }
        __syncthreads();
    }

    // epilogue: add bias, store float2 pairs
#pragma unroll
    for (int mt = 0; mt < 4; mt++) {
        int r0 = rowBase + wm * 64 + mt * 16 + g;
#pragma unroll
        for (int nt = 0; nt < 4; nt++) {
            int cc = colBase + wn * 32 + nt * 8 + c * 2;
            float b0 = bias[cc], b1 = bias[cc + 1];
            if (r0 < cE) {
                float2 v = make_float2(acc[mt][nt][0] + b0, acc[mt][nt][1] + b1);
                *(float2*)(C + (size_t)r0 * cDSQ + cc) = v;
            }
            if (r0 + 8 < cE) {
                float2 v = make_float2(acc[mt][nt][2] + b0, acc[mt][nt][3] + b1);
                *(float2*)(C + (size_t)(r0 + 8) * cDSQ + cc) = v;
            }
        }
    }
}

// -------- generic tiled SGEMM (for the small node GEMMs) --------
template <int BM, int BN, int BK, int TM, int TN>
__global__ void sgemm(int M, int Nc, int K,
                      const float* __restrict__ A, const float* __restrict__ Bw,
                      const float* __restrict__ bias, float* __restrict__ C) {
    constexpr int NT = (BM / TM) * (BN / TN);
    __shared__ float As[BK][BM];
    __shared__ float Bs[BK][BN];
    const int tid = threadIdx.x;
    const int tcn = BN / TN;
    const int tr = tid / tcn, tc = tid % tcn;
    const int rowBase = blockIdx.y * BM, colBase = blockIdx.x * BN;

    float acc[TM][TN];
#pragma unroll
    for (int i = 0; i < TM; i++)
#pragma unroll
        for (int j = 0; j < TN; j++) acc[i][j] = 0.0f;

    for (int k0 = 0; k0 < K; k0 += BK) {
#pragma unroll
        for (int i = tid; i < BM * BK; i += NT) {
            int r = i / BK, kk = i % BK;
            int gr = rowBase + r;
            As[kk][r] = (gr < M) ? A[(size_t)gr * K + k0 + kk] : 0.0f;
        }
#pragma unroll
        for (int i = tid; i < BK * BN; i += NT) {
            int kk = i / BN, cc2 = i % BN;
            int gc = colBase + cc2;
            Bs[kk][cc2] = (gc < Nc) ? Bw[(size_t)(k0 + kk) * Nc + gc] : 0.0f;
        }
        __syncthreads();
#pragma unroll
        for (int kk = 0; kk < BK; kk++) {
            float ra[TM], rb[TN];
#pragma unroll
            for (int i = 0; i < TM; i++) ra[i] = As[kk][tr * TM + i];
#pragma unroll
            for (int j = 0; j < TN; j++) rb[j] = Bs[kk][tc * TN + j];
#pragma unroll
            for (int i = 0; i < TM; i++)
#pragma unroll
                for (int j = 0; j < TN; j++) acc[i][j] += ra[i] * rb[j];
        }
        __syncthreads();
    }
#pragma unroll
    for (int i = 0; i < TM; i++) {
        int r = rowBase + tr * TM + i;
        if (r >= M) continue;
#pragma unroll
        for (int j = 0; j < TN; j++) {
            int cc2 = colBase + tc * TN + j;
            if (cc2 >= Nc) continue;
            float v = acc[i][j] + (bias ? bias[cc2] : 0.0f);
            C[(size_t)r * Nc + cc2] = v;
        }
    }
}

// -------- per-edge matvec + scatter: agg[dst] += out[src] @ ew[e] --------
__global__ void k_msg(const float* __restrict__ out, const float* __restrict__ ew,
                      const int* __restrict__ src, const int* __restrict__ dst,
                      float* __restrict__ agg) {
    int e = blockIdx.x * blockDim.y + threadIdx.y;
    if (e >= cE) return;
    int lane = threadIdx.x;
    int s = src[e];
    const float* vo = out + s * cD;
    const float* w = ew + (size_t)e * cDSQ;
    float a0 = 0.0f, a1 = 0.0f;
#pragma unroll 8
    for (int i = 0; i < cD; i++) {
        float v = __ldg(vo + i);
        a0 += v * w[i * cD + lane];
        a1 += v * w[i * cD + 32 + lane];
    }
    int dn = dst[e];
    atomicAdd(&agg[dn * cD + lane], a0);
    atomicAdd(&agg[dn * cD + 32 + lane], a1);
}

__global__ void k_m(const float* __restrict__ agg, const float* __restrict__ croot,
                    const float* __restrict__ deg, const float* __restrict__ cbias,
                    float* __restrict__ m) {
    int idx = blockIdx.x * blockDim.x + threadIdx.x;
    if (idx >= cN * cD) return;
    int n = idx >> 6, d = idx & 63;
    float dg = fmaxf(deg[n], 1.0f);
    float v = agg[idx] / dg + croot[idx] + cbias[d];
    m[idx] = fmaxf(v, 0.0f);
}

__global__ void k_gate(const float* __restrict__ G1, const float* __restrict__ G2,
                       const float* __restrict__ h, float* __restrict__ hn) {
    int idx = blockIdx.x * blockDim.x + threadIdx.x;
    if (idx >= cN * cD) return;
    int n = idx >> 6, d = idx & 63;
    const float* g1 = G1 + n * 3 * cD;
    const float* g2 = G2 + n * 3 * cD;
    float r = sigm(g1[d] + g2[d]);
    float z = sigm(g1[cD + d] + g2[cD + d]);
    float nn = tanhf(g1[2 * cD + d] + r * g2[2 * cD + d]);
    hn[idx] = (1.0f - z) * nn + z * h[idx];
}

// ---------------- Set2Set ----------------
__global__ void k_s2s_init(float* qsA, float* hlA, float* clA) {
    int i = blockIdx.x * blockDim.x + threadIdx.x;
    if (i < cB * 2 * cD) qsA[i] = 0.0f;
    if (i < cB * cD) { hlA[i] = 0.0f; clA[i] = 0.0f; }
}

__global__ void k_lstm(const float* __restrict__ qs, const float* __restrict__ hl,
                       const float* __restrict__ cl,
                       const float* __restrict__ w_ih, const float* __restrict__ w_hh,
                       const float* __restrict__ b_ih, const float* __restrict__ b_hh,
                       float* __restrict__ hl_n, float* __restrict__ cl_n) {
    int idx = blockIdx.x * blockDim.x + threadIdx.x;
    if (idx >= cB * cD) return;
    int b = idx >> 6, d = idx & 63;
    float acc0 = b_ih[d] + b_hh[d];
    float acc1 = b_ih[cD + d] + b_hh[cD + d];
    float acc2 = b_ih[2 * cD + d] + b_hh[2 * cD + d];
    float acc3 = b_ih[3 * cD + d] + b_hh[3 * cD + d];
    const float* q = qs + b * 2 * cD;
#pragma unroll 4
    for (int k = 0; k < 2 * cD; k++) {
        float qv = q[k];
        const float* wr = w_ih + k * 4 * cD;
        acc0 += qv * wr[d];
        acc1 += qv * wr[cD + d];
        acc2 += qv * wr[2 * cD + d];
        acc3 += qv * wr[3 * cD + d];
    }
    const float* hr = hl + b * cD;
#pragma unroll 4
    for (int k = 0; k < cD; k++) {
        float hv = hr[k];
        const float* wr = w_hh + k * 4 * cD;
        acc0 += hv * wr[d];
        acc1 += hv * wr[cD + d];
        acc2 += hv * wr[2 * cD + d];
        acc3 += hv * wr[3 * cD + d];
    }
    float ig = sigm(acc0), fg = sigm(acc1), gg = tanhf(acc2), og = sigm(acc3);
    float cc2 = fg * cl[idx] + ig * gg;
    cl_n[idx] = cc2;
    hl_n[idx] = og * tanhf(cc2);
}

__global__ void k_zero_bat(unsigned* emaxu, float* esum, float* rvec) {
    int i = blockIdx.x * blockDim.x + threadIdx.x;
    if (i < cB) { emaxu[i] = 0u; esum[i] = 0.0f; }
    if (i < cB * cD) rvec[i] = 0.0f;
}

__global__ void k_attn1(const float* __restrict__ out, const int* __restrict__ batch,
                        const float* __restrict__ hl, float* __restrict__ esc,
                        unsigned* __restrict__ emaxu) {
    int n = blockIdx.x * blockDim.x + threadIdx.x;
    if (n >= cN) return;
    int b = batch[n];
    const float* o = out + n * cD;
    const float* q = hl + b * cD;
    float acc = 0.0f;
#pragma unroll 8
    for (int d = 0; d < cD; d++) acc += o[d] * q[d];
    esc[n] = acc;
    atomicMax(&emaxu[b], f2u(acc));
}

__global__ void k_attn2(const int* __restrict__ batch, float* __restrict__ esc,
                        const unsigned* __restrict__ emaxu, float* __restrict__ esum) {
    int n = blockIdx.x * blockDim.x + threadIdx.x;
    if (n >= cN) return;
    int b = batch[n];
    float ee = expf(esc[n] - u2f(emaxu[b]));
    esc[n] = ee;
    atomicAdd(&esum[b], ee);
}

__global__ void k_attn3(const float* __restrict__ out, const int* __restrict__ batch,
                        const float* __restrict__ esc, const float* __restrict__ esum,
                        float* __restrict__ rvec) {
    int idx = blockIdx.x * blockDim.x + threadIdx.x;
    if (idx >= cN * cD) return;
    int n = idx >> 6, d = idx & 63;
    int b = batch[n];
    float a = esc[n] / esum[b];
    atomicAdd(&rvec[b * cD + d], a * out[idx]);
}

__global__ void k_qstar(const float* __restrict__ hl, const float* __restrict__ rvec,
                        float* __restrict__ qs_n) {
    int idx = blockIdx.x * blockDim.x + threadIdx.x;
    if (idx >= cB * 2 * cD) return;
    int b = idx >> 7, c = idx & 127;
    qs_n[idx] = (c < cD) ? hl[b * cD + c] : rvec[b * cD + (c - cD)];
}

__global__ void k_lin1(const float* __restrict__ qs, const float* __restrict__ w,
                       const float* __restrict__ b, float* __restrict__ out) {
    int idx = blockIdx.x * blockDim.x + threadIdx.x;
    if (idx >= cB * cD) return;
    int bb = idx >> 6, d = idx & 63;
    float acc = b[d];
    const float* q = qs + bb * 2 * cD;
#pragma unroll 8
    for (int k = 0; k < 2 * cD; k++) acc += q[k] * w[k * cD + d];
    out[idx] = fmaxf(acc, 0.0f);
}

// ---------------- launch ----------------
extern "C" void kernel_launch(void* const* d_in, const int* in_sizes, int n_in,
                              void* d_out, int out_size) {
    const float* x        = (const float*)d_in[0];
    const float* ea       = (const float*)d_in[1];
    const int*   ei       = (const int*)d_in[2];
    const int*   batch    = (const int*)d_in[3];
    const float* lin0_w   = (const float*)d_in[4];
    const float* lin0_b   = (const float*)d_in[5];
    const float* net_w1   = (const float*)d_in[6];
    const float* net_b1   = (const float*)d_in[7];
    const float* net_w2   = (const float*)d_in[8];
    const float* net_b2   = (const float*)d_in[9];
    const float* conv_root= (const float*)d_in[10];
    const float* conv_bias= (const float*)d_in[11];
    const float* gru_w_ih = (const float*)d_in[12];
    const float* gru_w_hh = (const float*)d_in[13];
    const float* gru_b_ih = (const float*)d_in[14];
    const float* gru_b_hh = (const float*)d_in[15];
    const float* lstm_w_ih= (const float*)d_in[16];
    const float* lstm_w_hh= (const float*)d_in[17];
    const float* lstm_b_ih= (const float*)d_in[18];
    const float* lstm_b_hh= (const float*)d_in[19];
    const float* lin1_w   = (const float*)d_in[20];
    const float* lin1_b   = (const float*)d_in[21];
    float* out = (float*)d_out;

    const int* src = ei;
    const int* dst = ei + cE;

    void* p;
    cudaGetSymbolAddress(&p, g_h0);    float* p_h0 = (float*)p;
    cudaGetSymbolAddress(&p, g_h1);    float* p_h1 = (float*)p;
    cudaGetSymbolAddress(&p, g_hrelu); float* p_hr = (float*)p;
    cudaGetSymbolAddress(&p, g_ew);    float* p_ew = (float*)p;
    cudaGetSymbolAddress(&p, g_agg);   float* p_agg = (float*)p;
    cudaGetSymbolAddress(&p, g_m);     float* p_m = (float*)p;
    cudaGetSymbolAddress(&p, g_croot); float* p_cr = (float*)p;
    cudaGetSymbolAddress(&p, g_G1);    float* p_G1 = (float*)p;
    cudaGetSymbolAddress(&p, g_G2);    float* p_G2 = (float*)p;
    cudaGetSymbolAddress(&p, g_deg);   float* p_deg = (float*)p;
    cudaGetSymbolAddress(&p, g_esc);   float* p_esc = (float*)p;
    cudaGetSymbolAddress(&p, g_emaxu); unsigned* p_emax = (unsigned*)p;
    cudaGetSymbolAddress(&p, g_esum);  float* p_esum = (float*)p;
    cudaGetSymbolAddress(&p, g_rvec);  float* p_rvec = (float*)p;
    cudaGetSymbolAddress(&p, g_qsA);   float* p_qsA = (float*)p;
    cudaGetSymbolAddress(&p, g_qsB);   float* p_qsB = (float*)p;
    cudaGetSymbolAddress(&p, g_hlA);   float* p_hlA = (float*)p;
    cudaGetSymbolAddress(&p, g_hlB);   float* p_hlB = (float*)p;
    cudaGetSymbolAddress(&p, g_clA);   float* p_clA = (float*)p;
    cudaGetSymbolAddress(&p, g_clB);   float* p_clB = (float*)p;

    const int T = 256;

    // degree
    k_deg_zero<<<(cN + T - 1) / T, T>>>(p_deg);
    k_deg<<<(cE + T - 1) / T, T>>>(dst, p_deg);

    // lin0 -> h0
    k_lin0<<<(cN * cD + T - 1) / T, T>>>(x, lin0_w, lin0_b, p_h0);

    // edge network: layer 1 then TF32 tensor-core GEMM for ew
    k_edge1<<<(cE * cH + T - 1) / T, T>>>(ea, net_w1, net_b1, p_hr);
    {
        dim3 grid(cDSQ / 128, (cE + 127) / 128);   // 32 x 313
        k_ewgemm<<<grid, 256>>>(p_hr, net_w2, net_b2, p_ew);
    }

    // 3 message-passing steps, ping-pong h between h0/h1
    for (int s = 0; s < 3; s++) {
        float* cur = (s & 1) ? p_h1 : p_h0;
        float* nxt = (s & 1) ? p_h0 : p_h1;
        k_zero<<<(cN * cD + T - 1) / T, T>>>(p_agg, cN * cD);
        {
            dim3 blk(32, 8);
            k_msg<<<(cE + 7) / 8, blk>>>(cur, p_ew, src, dst, p_agg);
        }
        {
            dim3 grid((cD + 63) / 64, (cN + 63) / 64);
            sgemm<64, 64, 8, 4, 4><<<grid, 256>>>(cN, cD, cD, cur, conv_root, (const float*)0, p_cr);
        }
        k_m<<<(cN * cD + T - 1) / T, T>>>(p_agg, p_cr, p_deg, conv_bias, p_m);
        {
            dim3 grid((3 * cD + 63) / 64, (cN + 63) / 64);
            sgemm<64, 64, 8, 4, 4><<<grid, 256>>>(cN, 3 * cD, cD, p_m, gru_w_ih, gru_b_ih, p_G1);
            sgemm<64, 64, 8, 4, 4><<<grid, 256>>>(cN, 3 * cD, cD, cur, gru_w_hh, gru_b_hh, p_G2);
        }
        k_gate<<<(cN * cD + T - 1) / T, T>>>(p_G1, p_G2, cur, nxt);
    }
    float* p_hfin = p_h1;

    // Set2Set
    k_s2s_init<<<(cB * 2 * cD + T - 1) / T, T>>>(p_qsA, p_hlA, p_clA);
    for (int t = 0; t < 3; t++) {
        float* qs_c = (t & 1) ? p_qsB : p_qsA;
        float* qs_n = (t & 1) ? p_qsA : p_qsB;
        float* hl_c = (t & 1) ? p_hlB : p_hlA;
        float* hl_n = (t & 1) ? p_hlA : p_hlB;
        float* cl_c = (t & 1) ? p_clB : p_clA;
        float* cl_n = (t & 1) ? p_clA : p_clB;

        k_lstm<<<(cB * cD + T - 1) / T, T>>>(qs_c, hl_c, cl_c, lstm_w_ih, lstm_w_hh,
                                             lstm_b_ih, lstm_b_hh, hl_n, cl_n);
        k_zero_bat<<<(cB * cD + T - 1) / T, T>>>(p_emax, p_esum, p_rvec);
        k_attn1<<<(cN + T - 1) / T, T>>>(p_hfin, batch, hl_n, p_esc, p_emax);
        k_attn2<<<(cN + T - 1) / T, T>>>(batch, p_esc, p_emax, p_esum);
        k_attn3<<<(cN * cD + T - 1) / T, T>>>(p_hfin, batch, p_esc, p_esum, p_rvec);
        k_qstar<<<(cB * 2 * cD + T - 1) / T, T>>>(hl_n, p_rvec, qs_n);
    }

    k_lin1<<<(cB * cD + T - 1) / T, T>>>(p_qsB, lin1_w, lin1_b, out);
}